// round 2
// baseline (speedup 1.0000x reference)
#include <cuda_runtime.h>
#include <cuda_bf16.h>
#include <cstdint>

// Problem constants (fixed shapes for this problem)
#define N_NODES_MAX 50000
#define F_IN 256
#define H_DIM 128   // H1 == H2 == 128

// ---------------------------------------------------------------------------
// Scratch (no cudaMalloc allowed): device globals.
// ---------------------------------------------------------------------------
__device__ float g_s1 [N_NODES_MAX * H_DIM];
__device__ float g_agg[2 * N_NODES_MAX * H_DIM];
__device__ float g_h1 [N_NODES_MAX * H_DIM];

// ---------------------------------------------------------------------------
// Zero-fill (grid-stride float4)
// ---------------------------------------------------------------------------
__global__ void zero_kernel(float4* __restrict__ p, int n4) {
    int i = blockIdx.x * blockDim.x + threadIdx.x;
    int stride = gridDim.x * blockDim.x;
    float4 z = make_float4(0.f, 0.f, 0.f, 0.f);
    for (; i < n4; i += stride) p[i] = z;
}

// ---------------------------------------------------------------------------
// Register-tiled SGEMM: C[M,128] = A[M,K] @ B[K,128]
// BM=128, BN=128 (==N), BK=8, 256 threads, TM=TN=8.
// ---------------------------------------------------------------------------
__global__ __launch_bounds__(256) void sgemm_n128(
    const float* __restrict__ A, const float* __restrict__ B,
    float* __restrict__ C, int M, int K)
{
    const int BM = 128, BK = 8, TM = 8, TN = 8;
    __shared__ float As[BK][BM];
    __shared__ float Bs[BK][128];

    int block_row = blockIdx.x * BM;
    int tid = threadIdx.x;              // 0..255
    int tx = tid & 15;                  // 16 thread-cols * TN=8 -> 128
    int ty = tid >> 4;                  // 16 thread-rows * TM=8 -> 128

    float acc[TM][TN];
    #pragma unroll
    for (int i = 0; i < TM; i++)
        #pragma unroll
        for (int j = 0; j < TN; j++) acc[i][j] = 0.f;

    // loader coords
    int ar = tid >> 1;                  // 0..127 (row within A tile)
    int ac = (tid & 1) * 4;             // 0 or 4 (k offset, float4)
    int br = tid >> 5;                  // 0..7   (k row within B tile)
    int bc = (tid & 31) * 4;            // 0..124 (col, float4)

    for (int k0 = 0; k0 < K; k0 += BK) {
        // A tile (transposed store: As[k][m])
        float4 av = make_float4(0.f, 0.f, 0.f, 0.f);
        int grow = block_row + ar;
        if (grow < M)
            av = *(const float4*)(A + (size_t)grow * K + k0 + ac);
        As[ac + 0][ar] = av.x;
        As[ac + 1][ar] = av.y;
        As[ac + 2][ar] = av.z;
        As[ac + 3][ar] = av.w;
        // B tile
        float4 bv = *(const float4*)(B + (size_t)(k0 + br) * 128 + bc);
        *(float4*)&Bs[br][bc] = bv;
        __syncthreads();

        #pragma unroll
        for (int k = 0; k < BK; k++) {
            float a[TM], b[TN];
            #pragma unroll
            for (int i = 0; i < TM; i++) a[i] = As[k][ty * TM + i];
            #pragma unroll
            for (int j = 0; j < TN; j++) b[j] = Bs[k][tx * TN + j];
            #pragma unroll
            for (int i = 0; i < TM; i++)
                #pragma unroll
                for (int j = 0; j < TN; j++)
                    acc[i][j] += a[i] * b[j];
        }
        __syncthreads();
    }

    #pragma unroll
    for (int i = 0; i < TM; i++) {
        int grow = block_row + ty * TM + i;
        if (grow < M) {
            float* crow = C + (size_t)grow * 128 + tx * TN;
            #pragma unroll
            for (int j = 0; j < TN; j += 4)
                *(float4*)(crow + j) =
                    make_float4(acc[i][j], acc[i][j+1], acc[i][j+2], acc[i][j+3]);
        }
    }
}

// ---------------------------------------------------------------------------
// SpMM scatter: out[rows[e]] += vals[e] * x[cols[e]]   (128 floats per edge)
// One warp per edge; each lane handles 4 contiguous columns via a single
// vector RED (red.global.add.v4.f32, sm_90+). Both x and out fit in L2.
// Grid-stride over edges.
// ---------------------------------------------------------------------------
__global__ __launch_bounds__(256) void spmm_scatter(
    const float* __restrict__ x, const int* __restrict__ rows,
    const int* __restrict__ cols, const float* __restrict__ vals,
    float* __restrict__ out, int n_edges)
{
    int lane = threadIdx.x & 31;
    int warp0 = (blockIdx.x * blockDim.x + threadIdx.x) >> 5;
    int nwarps = (gridDim.x * blockDim.x) >> 5;

    for (int e = warp0; e < n_edges; e += nwarps) {
        int r = __ldg(rows + e);
        int c = __ldg(cols + e);
        float v = __ldg(vals + e);

        float4 xv = *(const float4*)(x + (size_t)c * 128 + lane * 4);
        float4 o  = make_float4(xv.x * v, xv.y * v, xv.z * v, xv.w * v);
        float* p  = out + (size_t)r * 128 + lane * 4;

        asm volatile(
            "red.global.add.v4.f32 [%0], {%1, %2, %3, %4};"
            :: "l"(p), "f"(o.x), "f"(o.y), "f"(o.z), "f"(o.w)
            : "memory");
    }
}

// ---------------------------------------------------------------------------
// out[n, j] = relu(agg[n, j] + bias[j])
// ---------------------------------------------------------------------------
__global__ __launch_bounds__(256) void bias_relu(
    const float* __restrict__ agg, const float* __restrict__ bias,
    float* __restrict__ out, int total4)
{
    int i = blockIdx.x * blockDim.x + threadIdx.x;
    if (i >= total4) return;
    int j = (i & 31) * 4;   // column group within 128-wide row
    float4 a = *(const float4*)(agg + (size_t)i * 4);
    float4 b = *(const float4*)(bias + j);
    float4 o;
    o.x = fmaxf(a.x + b.x, 0.f);
    o.y = fmaxf(a.y + b.y, 0.f);
    o.z = fmaxf(a.z + b.z, 0.f);
    o.w = fmaxf(a.w + b.w, 0.f);
    *(float4*)(out + (size_t)i * 4) = o;
}

// ---------------------------------------------------------------------------
// Launch: zero -> gemm1 -> scatter1 -> bias_relu1 -> gemm2 -> scatter2 -> bias_relu2
// ---------------------------------------------------------------------------
extern "C" void kernel_launch(void* const* d_in, const int* in_sizes, int n_in,
                              void* d_out, int out_size)
{
    const float* features = (const float*)d_in[0];
    const int*   rows     = (const int*)  d_in[1];
    const int*   cols     = (const int*)  d_in[2];
    const float* vals     = (const float*)d_in[3];
    const float* W1       = (const float*)d_in[4];
    const float* b1       = (const float*)d_in[5];
    const float* W2       = (const float*)d_in[6];
    const float* b2       = (const float*)d_in[7];
    float* out = (float*)d_out;

    int M       = in_sizes[0] / F_IN;    // 50000
    int n_edges = in_sizes[1];           // 800000

    float *s1, *agg, *h1;
    cudaGetSymbolAddress((void**)&s1,  g_s1);
    cudaGetSymbolAddress((void**)&agg, g_agg);
    cudaGetSymbolAddress((void**)&h1,  g_h1);
    float* agg2 = agg + (size_t)M * H_DIM;

    // 1) zero both aggregation buffers (2 * M * 128 floats)
    {
        int n4 = 2 * M * H_DIM / 4;
        zero_kernel<<<1024, 256>>>((float4*)agg, n4);
    }

    // 2) support1 = X @ W1
    sgemm_n128<<<(M + 127) / 128, 256>>>(features, W1, s1, M, F_IN);

    // 3) agg1 = A @ support1
    {
        int warps_needed = n_edges;
        int blocks = min((warps_needed * 32 + 255) / 256, 16 * 1024);
        spmm_scatter<<<blocks, 256>>>(s1, rows, cols, vals, agg, n_edges);
    }

    // 4) h1 = relu(agg1 + b1)
    {
        int total4 = M * H_DIM / 4;
        bias_relu<<<(total4 + 255) / 256, 256>>>(agg, b1, h1, total4);
    }

    // 5) support2 = h1 @ W2 (reuse s1)
    sgemm_n128<<<(M + 127) / 128, 256>>>(h1, W2, s1, M, H_DIM);

    // 6) agg2 = A @ support2
    {
        int warps_needed = n_edges;
        int blocks = min((warps_needed * 32 + 255) / 256, 16 * 1024);
        spmm_scatter<<<blocks, 256>>>(s1, rows, cols, vals, agg2, n_edges);
    }

    // 7) out = relu(agg2 + b2)
    {
        int total4 = M * H_DIM / 4;
        bias_relu<<<(total4 + 255) / 256, 256>>>(agg2, b2, out, total4);
    }
}

// round 10
// speedup vs baseline: 1.2110x; 1.2110x over previous
#include <cuda_runtime.h>
#include <cuda_bf16.h>
#include <mma.h>
#include <cstdint>

using namespace nvcuda;

#define N_NODES_MAX 50000
#define N_EDGES_MAX 800000
#define F_IN 256
#define H_DIM 128

// ---------------------------------------------------------------------------
// Scratch (__device__ globals; no cudaMalloc allowed)
// ---------------------------------------------------------------------------
__device__ float g_s1 [N_NODES_MAX * H_DIM];     // GEMM output (support)
__device__ float g_h1 [N_NODES_MAX * H_DIM];     // hidden activations
__device__ int   g_counts [N_NODES_MAX];
__device__ int   g_rowstart[N_NODES_MAX + 1];
__device__ int   g_cursor [N_NODES_MAX];
__device__ int   g_csr_col[N_EDGES_MAX];
__device__ float g_csr_val[N_EDGES_MAX];

// ---------------------------------------------------------------------------
// CSR build
// ---------------------------------------------------------------------------
__global__ void zero_counts(int* __restrict__ counts, int n) {
    int i = blockIdx.x * blockDim.x + threadIdx.x;
    int stride = gridDim.x * blockDim.x;
    for (; i < n; i += stride) counts[i] = 0;
}

__global__ void hist_rows(const int* __restrict__ rows, int* __restrict__ counts,
                          int n_edges) {
    int i = blockIdx.x * blockDim.x + threadIdx.x;
    int stride = gridDim.x * blockDim.x;
    for (; i < n_edges; i += stride) atomicAdd(&counts[rows[i]], 1);
}

__global__ __launch_bounds__(1024) void scan_counts(
    const int* __restrict__ counts, int* __restrict__ row_start,
    int* __restrict__ cursor, int n, int n_edges)
{
    __shared__ int ssum[1024];
    int tid = threadIdx.x;
    int chunk = (n + 1023) / 1024;
    int begin = tid * chunk;
    int end = min(begin + chunk, n);

    int s = 0;
    for (int i = begin; i < end; i++) s += counts[i];
    ssum[tid] = s;
    __syncthreads();

    #pragma unroll
    for (int off = 1; off < 1024; off <<= 1) {
        int v = (tid >= off) ? ssum[tid - off] : 0;
        __syncthreads();
        ssum[tid] += v;
        __syncthreads();
    }

    int offset = (tid == 0) ? 0 : ssum[tid - 1];
    for (int i = begin; i < end; i++) {
        row_start[i] = offset;
        cursor[i]    = offset;
        offset += counts[i];
    }
    if (tid == 0) row_start[n] = n_edges;
}

__global__ void fill_csr(const int* __restrict__ rows, const int* __restrict__ cols,
                         const float* __restrict__ vals, int* __restrict__ cursor,
                         int* __restrict__ csr_col, float* __restrict__ csr_val,
                         int n_edges)
{
    int i = blockIdx.x * blockDim.x + threadIdx.x;
    int stride = gridDim.x * blockDim.x;
    for (; i < n_edges; i += stride) {
        int r = rows[i];
        int pos = atomicAdd(&cursor[r], 1);
        csr_col[pos] = cols[i];
        csr_val[pos] = vals[i];
    }
}

// ---------------------------------------------------------------------------
// TF32 WMMA GEMM: C[M,128] = A[M,K] @ B[K,128]   (fp32 in/out, tf32 mma)
// Block: 128x128 output, 256 threads = 8 warps in 2x4 (row x col).
// Warp: 64x32 output = 4x2 grid of 16x16x8 wmma tiles. BK chunk = 32.
// M is a multiple of 16 (50000 = 3125*16) -> no partial wmma tiles;
// A-tile rows beyond M are zero-filled, stores guarded per 16-row tile.
// ---------------------------------------------------------------------------
__global__ __launch_bounds__(256) void sgemm_tf32_n128(
    const float* __restrict__ A, const float* __restrict__ B,
    float* __restrict__ C, int M, int K)
{
    const int BKC = 32;
    __shared__ float As[128][36];   // padded: ldm 36 (144 B rows, 16B aligned)
    __shared__ float Bs[32][128];

    int tid = threadIdx.x;
    int warp_id = tid >> 5;
    int warp_row = warp_id & 1;     // 0..1  -> rows warp_row*64
    int warp_col = warp_id >> 1;    // 0..3  -> cols warp_col*32
    int block_row = blockIdx.x * 128;

    wmma::fragment<wmma::accumulator, 16, 16, 8, float> c_frag[4][2];
    #pragma unroll
    for (int tr = 0; tr < 4; tr++)
        #pragma unroll
        for (int tc = 0; tc < 2; tc++)
            wmma::fill_fragment(c_frag[tr][tc], 0.0f);

    for (int k0 = 0; k0 < K; k0 += BKC) {
        // load A tile (128x32) and B tile (32x128), float4 per thread x4
        #pragma unroll
        for (int i = 0; i < 4; i++) {
            int idx = tid + i * 256;          // 0..1023
            int arow = idx >> 3;              // /8 (8 float4 per 32-col row)
            int acol = (idx & 7) * 4;
            float4 av = make_float4(0.f, 0.f, 0.f, 0.f);
            if (block_row + arow < M)
                av = *(const float4*)(A + (size_t)(block_row + arow) * K + k0 + acol);
            *(float4*)&As[arow][acol] = av;

            int brow = idx >> 5;              // /32 (32 float4 per 128-col row)
            int bcol = (idx & 31) * 4;
            *(float4*)&Bs[brow][bcol] =
                *(const float4*)(B + (size_t)(k0 + brow) * 128 + bcol);
        }
        __syncthreads();

        #pragma unroll
        for (int ks = 0; ks < 4; ks++) {      // 4 k-steps of 8
            wmma::fragment<wmma::matrix_b, 16, 16, 8, wmma::precision::tf32,
                           wmma::row_major> b_frag[2];
            #pragma unroll
            for (int tc = 0; tc < 2; tc++) {
                wmma::load_matrix_sync(b_frag[tc],
                    &Bs[ks * 8][warp_col * 32 + tc * 16], 128);
                #pragma unroll
                for (int t = 0; t < b_frag[tc].num_elements; t++)
                    b_frag[tc].x[t] = wmma::__float_to_tf32(b_frag[tc].x[t]);
            }
            #pragma unroll
            for (int tr = 0; tr < 4; tr++) {
                wmma::fragment<wmma::matrix_a, 16, 16, 8, wmma::precision::tf32,
                               wmma::row_major> a_frag;
                wmma::load_matrix_sync(a_frag,
                    &As[warp_row * 64 + tr * 16][ks * 8], 36);
                #pragma unroll
                for (int t = 0; t < a_frag.num_elements; t++)
                    a_frag.x[t] = wmma::__float_to_tf32(a_frag.x[t]);
                #pragma unroll
                for (int tc = 0; tc < 2; tc++)
                    wmma::mma_sync(c_frag[tr][tc], a_frag, b_frag[tc],
                                   c_frag[tr][tc]);
            }
        }
        __syncthreads();
    }

    #pragma unroll
    for (int tr = 0; tr < 4; tr++) {
        int grow = block_row + warp_row * 64 + tr * 16;
        if (grow < M) {   // M % 16 == 0 -> whole 16-row tile valid
            #pragma unroll
            for (int tc = 0; tc < 2; tc++)
                wmma::store_matrix_sync(
                    C + (size_t)grow * 128 + warp_col * 32 + tc * 16,
                    c_frag[tr][tc], 128, wmma::mem_row_major);
        }
    }
}

// ---------------------------------------------------------------------------
// Gather SpMM + bias + relu (one warp per row, float4 lanes, unroll 4)
// ---------------------------------------------------------------------------
__global__ __launch_bounds__(256) void spmm_gather_bias_relu(
    const float* __restrict__ x, const int* __restrict__ row_start,
    const int* __restrict__ csr_col, const float* __restrict__ csr_val,
    const float* __restrict__ bias, float* __restrict__ out, int n_rows)
{
    int warp = (blockIdx.x * blockDim.x + threadIdx.x) >> 5;
    int lane = threadIdx.x & 31;
    if (warp >= n_rows) return;

    int s = row_start[warp];
    int e = row_start[warp + 1];

    const float4* x4 = (const float4*)x;
    float4 acc = make_float4(0.f, 0.f, 0.f, 0.f);

    int i = s;
    for (; i + 4 <= e; i += 4) {
        int   c0 = __ldg(csr_col + i + 0);
        int   c1 = __ldg(csr_col + i + 1);
        int   c2 = __ldg(csr_col + i + 2);
        int   c3 = __ldg(csr_col + i + 3);
        float v0 = __ldg(csr_val + i + 0);
        float v1 = __ldg(csr_val + i + 1);
        float v2 = __ldg(csr_val + i + 2);
        float v3 = __ldg(csr_val + i + 3);
        float4 x0 = __ldg(x4 + (size_t)c0 * 32 + lane);
        float4 x1 = __ldg(x4 + (size_t)c1 * 32 + lane);
        float4 x2 = __ldg(x4 + (size_t)c2 * 32 + lane);
        float4 x3 = __ldg(x4 + (size_t)c3 * 32 + lane);
        acc.x += v0 * x0.x; acc.y += v0 * x0.y; acc.z += v0 * x0.z; acc.w += v0 * x0.w;
        acc.x += v1 * x1.x; acc.y += v1 * x1.y; acc.z += v1 * x1.z; acc.w += v1 * x1.w;
        acc.x += v2 * x2.x; acc.y += v2 * x2.y; acc.z += v2 * x2.z; acc.w += v2 * x2.w;
        acc.x += v3 * x3.x; acc.y += v3 * x3.y; acc.z += v3 * x3.z; acc.w += v3 * x3.w;
    }
    for (; i < e; i++) {
        int   c = __ldg(csr_col + i);
        float v = __ldg(csr_val + i);
        float4 xv = __ldg(x4 + (size_t)c * 32 + lane);
        acc.x += v * xv.x; acc.y += v * xv.y; acc.z += v * xv.z; acc.w += v * xv.w;
    }

    float4 b = __ldg((const float4*)bias + lane);
    float4 o;
    o.x = fmaxf(acc.x + b.x, 0.f);
    o.y = fmaxf(acc.y + b.y, 0.f);
    o.z = fmaxf(acc.z + b.z, 0.f);
    o.w = fmaxf(acc.w + b.w, 0.f);
    ((float4*)out)[(size_t)warp * 32 + lane] = o;
}

// ---------------------------------------------------------------------------
// Launch sequence
// ---------------------------------------------------------------------------
extern "C" void kernel_launch(void* const* d_in, const int* in_sizes, int n_in,
                              void* d_out, int out_size)
{
    const float* features = (const float*)d_in[0];
    const int*   rows     = (const int*)  d_in[1];
    const int*   cols     = (const int*)  d_in[2];
    const float* vals     = (const float*)d_in[3];
    const float* W1       = (const float*)d_in[4];
    const float* b1       = (const float*)d_in[5];
    const float* W2       = (const float*)d_in[6];
    const float* b2       = (const float*)d_in[7];
    float* out = (float*)d_out;

    int M       = in_sizes[0] / F_IN;    // 50000
    int n_edges = in_sizes[1];           // 800000

    float *s1, *h1, *csr_val;
    int *counts, *row_start, *cursor, *csr_col;
    cudaGetSymbolAddress((void**)&s1,        g_s1);
    cudaGetSymbolAddress((void**)&h1,        g_h1);
    cudaGetSymbolAddress((void**)&counts,    g_counts);
    cudaGetSymbolAddress((void**)&row_start, g_rowstart);
    cudaGetSymbolAddress((void**)&cursor,    g_cursor);
    cudaGetSymbolAddress((void**)&csr_col,   g_csr_col);
    cudaGetSymbolAddress((void**)&csr_val,   g_csr_val);

    // --- CSR build (once; reused by both SpMM passes) ---
    zero_counts<<<(M + 255) / 256, 256>>>(counts, M);
    hist_rows  <<<592, 256>>>(rows, counts, n_edges);
    scan_counts<<<1, 1024>>>(counts, row_start, cursor, M, n_edges);
    fill_csr   <<<592, 256>>>(rows, cols, vals, cursor, csr_col, csr_val, n_edges);

    int gemm_blocks = (M + 127) / 128;   // 391

    // --- Layer 1 ---
    sgemm_tf32_n128<<<gemm_blocks, 256>>>(features, W1, s1, M, F_IN);
    spmm_gather_bias_relu<<<(M * 32 + 255) / 256, 256>>>(
        s1, row_start, csr_col, csr_val, b1, h1, M);

    // --- Layer 2 ---
    sgemm_tf32_n128<<<gemm_blocks, 256>>>(h1, W2, s1, M, H_DIM);
    spmm_gather_bias_relu<<<(M * 32 + 255) / 256, 256>>>(
        s1, row_start, csr_col, csr_val, b2, out, M);
}